// round 16
// baseline (speedup 1.0000x reference)
#include <cuda_runtime.h>
#include <cuda_fp16.h>
#include <math.h>
#include <stdint.h>

// Problem constants
#define BB 32
#define TT 64
#define EE 512
#define HH 512
#define VV 32000
#define NSTEP 63              // T-1 timesteps
#define MM (NSTEP * BB)       // 2016 rows
#define G4 (4 * HH)           // 2048 gate columns
#define KK 512

// -------------------- device scratch (no allocs allowed) --------------------
__device__ __half g_xseq_h[MM * EE];          // fp16 LSTM inputs (GEMM-A of gemm0)
__device__ __half g_wih_h[G4 * KK];           // fp16 W_ih
__device__ __half g_fcw_h[(size_t)VV * KK];   // fp16 fc_w (32MB)
__device__ __half g_hs_h[MM * HH];            // fp16 hidden states (GEMM-A of gemmC)
__device__ float  g_pre[(size_t)MM * G4];     // pre-gates (x@W_ih^T + both biases)
__device__ float  g_h[2][BB * HH];            // double-buffered h (fp32 exact)
__device__ float  g_c[BB * HH];               // cell state
__device__ int    g_cap64;                    // 1 if captions buffer is int64

// -------------------- dtype detect for captions --------------------
__global__ void detect_cap64(const int* cap) {
    if (threadIdx.x == 0) {
        int f = 1;
        for (int i = 0; i < 32; i++)
            if (cap[2 * i + 1] != 0) { f = 0; break; }
        g_cap64 = f;
    }
}

// -------------------- init h/c to zero (graph-replay determinism) ----------
__global__ void init_state() {
    int i = blockIdx.x * blockDim.x + threadIdx.x;
    if (i < BB * HH) { g_h[0][i] = 0.f; g_c[i] = 0.f; }
}

// -------------------- zero out[:, 0, :] --------------------
__global__ void zero_out0(float* out) {
    int b  = blockIdx.y;
    int vv = blockIdx.x * 256 + threadIdx.x;
    if (vv < VV) out[(size_t)b * TT * VV + vv] = 0.f;
}

// -------------------- fp16 pack helper --------------------
__device__ __forceinline__ uint32_t f2h2(float e0, float e1) {
    union { __half2 h; uint32_t u; } x;
    x.h = __floats2half2_rn(e0, e1);
    return x.u;
}

// -------------------- fp32 -> fp16 conversion (4 elems/thread) --------------
__global__ void to_half4(const float* __restrict__ s, __half* __restrict__ d,
                         int n4) {
    int i = blockIdx.x * 256 + threadIdx.x;
    if (i < n4) {
        float4 v = ((const float4*)s)[i];
        uint2 o;
        o.x = f2h2(v.x, v.y);
        o.y = f2h2(v.z, v.w);
        ((uint2*)d)[i] = o;
    }
}

// -------------------- build x_seq (fp16): [t=0]=features, else embed ---------
__global__ void build_xseq(const float* __restrict__ features,
                           const void*  __restrict__ cap,
                           const float* __restrict__ embed) {
    int i = blockIdx.x;   // 0..62
    int b = blockIdx.y;   // 0..31
    int col = threadIdx.x * 4;
    const float* src;
    if (i == 0) {
        src = features + (size_t)b * EE;
    } else {
        long long idx;
        if (g_cap64) idx = ((const long long*)cap)[b * TT + i + 1];
        else         idx = ((const int*)cap)[b * TT + i + 1];
        src = embed + (size_t)idx * EE;
    }
    float4 v = *(const float4*)&src[col];
    uint2 o;
    o.x = f2h2(v.x, v.y);
    o.y = f2h2(v.z, v.w);
    *(uint2*)&g_xseq_h[((size_t)i * BB + b) * EE + col] = o;
}

// -------------------- fp16 GEMM: out = A @ B^T + bias (R14-PROVEN core) -----
// Identical fragment maps / pipeline / mma to R14; only change: operands are
// pre-converted fp16 in global, so the mainloop loads are direct uint4 copies
// (bit-identical smem contents, zero cvt work, half the load bytes).
// MODE 0: A=g_xseq_h, out=g_pre[m][n],             bias = bias1[n]+bias2[n]
// MODE 1: A=g_hs_h,   out=d_out[(b*64 + t+1)][n],  bias = bias1[n]  (m = t*32+b)
#define LDW 20        // u32 row stride in smem (16 + 4 pad)
template <int MODE, int N>
__global__ void __launch_bounds__(256)
gemm_f16(const __half* __restrict__ Bmat,
         const float* __restrict__ bias1,
         const float* __restrict__ bias2,
         float* __restrict__ outc) {
    constexpr int BM = 128, BN = 128, BK = 32, NT = KK / BK;   // 16 tiles
    __shared__ uint32_t sA[2][BM][LDW];
    __shared__ uint32_t sB[2][BN][LDW];

    const __half* Amat = (MODE == 0) ? g_xseq_h : g_hs_h;
    float*        Out  = (MODE == 0) ? g_pre    : outc;

    int tid  = threadIdx.x;
    int wid  = tid >> 5, lane = tid & 31;
    int wm   = wid & 3,  wn   = wid >> 2;      // 4x2 warp grid, warp tile 32x64
    int grp  = lane >> 2, tig = lane & 3;
    int m0   = blockIdx.y * BM, n0 = blockIdx.x * BN;

    int lrow[2], lqc[2]; bool aval[2];
    const __half *aptr[2], *bptr[2];
#pragma unroll
    for (int l = 0; l < 2; l++) {
        int s = tid + l * 256;
        lrow[l] = s >> 2; lqc[l] = s & 3;
        int gm = m0 + lrow[l];
        aval[l] = (gm < MM);
        aptr[l] = Amat + (size_t)(aval[l] ? gm : 0) * KK + lqc[l] * 8;
        bptr[l] = Bmat + (size_t)(n0 + lrow[l]) * KK + lqc[l] * 8;
    }

    uint32_t sA0 = (uint32_t)__cvta_generic_to_shared(&sA[0][0][0]);
    uint32_t sB0 = (uint32_t)__cvta_generic_to_shared(&sB[0][0][0]);
    uint32_t aoff = (uint32_t)((wm * 32 + (lane & 15)) * LDW + (lane >> 4) * 4);
    uint32_t boff = (uint32_t)((wn * 64 + (lane >> 4) * 8 + (lane & 7)) * LDW
                               + ((lane >> 3) & 1) * 4);

    float c[2][8][4];
#pragma unroll
    for (int mi = 0; mi < 2; mi++)
#pragma unroll
        for (int ni = 0; ni < 8; ni++)
#pragma unroll
            for (int r = 0; r < 4; r++) c[mi][ni][r] = 0.f;

    uint4 apack[2], bpack[2];
    const uint4 ZV = make_uint4(0u, 0u, 0u, 0u);

#define LOADREGS(KT) do {                                                     \
        int k0 = (KT) * BK;                                                   \
        _Pragma("unroll")                                                     \
        for (int l = 0; l < 2; l++) {                                         \
            apack[l] = aval[l] ? *(const uint4*)(aptr[l] + k0) : ZV;          \
            bpack[l] = *(const uint4*)(bptr[l] + k0);                         \
        }                                                                     \
    } while (0)
#define STOREST(BUF) do {                                                     \
        _Pragma("unroll")                                                     \
        for (int l = 0; l < 2; l++) {                                         \
            *(uint4*)&sA[BUF][lrow[l]][lqc[l] * 4] = apack[l];                \
            *(uint4*)&sB[BUF][lrow[l]][lqc[l] * 4] = bpack[l];                \
        }                                                                     \
    } while (0)

    LOADREGS(0);
    STOREST(0);
    LOADREGS(1);
    __syncthreads();

#pragma unroll 1
    for (int kt = 0; kt < NT; kt++) {
        int cb = kt & 1;
        if (kt + 1 < NT) STOREST((kt + 1) & 1);
        if (kt + 2 < NT) LOADREGS(kt + 2);

        uint32_t sAb = sA0 + (uint32_t)(cb * BM * LDW * 4);
        uint32_t sBb = sB0 + (uint32_t)(cb * BN * LDW * 4);
#pragma unroll
        for (int ks = 0; ks < 2; ks++) {
            uint32_t kadd = (uint32_t)(ks * 8 * 4);
            uint32_t a[2][4], bf[8][2];
#pragma unroll
            for (int mi = 0; mi < 2; mi++) {
                uint32_t addr = sAb + (aoff + (uint32_t)(mi * 16 * LDW)) * 4 + kadd;
                asm volatile(
                    "ldmatrix.sync.aligned.m8n8.x4.shared.b16 {%0,%1,%2,%3}, [%4];"
                    : "=r"(a[mi][0]), "=r"(a[mi][1]), "=r"(a[mi][2]), "=r"(a[mi][3])
                    : "r"(addr));
            }
#pragma unroll
            for (int nj = 0; nj < 4; nj++) {
                uint32_t addr = sBb + (boff + (uint32_t)(nj * 16 * LDW)) * 4 + kadd;
                asm volatile(
                    "ldmatrix.sync.aligned.m8n8.x4.shared.b16 {%0,%1,%2,%3}, [%4];"
                    : "=r"(bf[2 * nj][0]), "=r"(bf[2 * nj][1]),
                      "=r"(bf[2 * nj + 1][0]), "=r"(bf[2 * nj + 1][1])
                    : "r"(addr));
            }
#pragma unroll
            for (int mi = 0; mi < 2; mi++)
#pragma unroll
                for (int ni = 0; ni < 8; ni++) {
                    asm volatile(
                        "mma.sync.aligned.m16n8k16.row.col.f32.f16.f16.f32 "
                        "{%0,%1,%2,%3}, {%4,%5,%6,%7}, {%8,%9}, {%0,%1,%2,%3};"
                        : "+f"(c[mi][ni][0]), "+f"(c[mi][ni][1]),
                          "+f"(c[mi][ni][2]), "+f"(c[mi][ni][3])
                        : "r"(a[mi][0]), "r"(a[mi][1]), "r"(a[mi][2]), "r"(a[mi][3]),
                          "r"(bf[ni][0]), "r"(bf[ni][1]));
                }
        }
        __syncthreads();
    }
#undef LOADREGS
#undef STOREST

    // epilogue (proven; C fragment layout unchanged)
#pragma unroll
    for (int mi = 0; mi < 2; mi++) {
#pragma unroll
        for (int ni = 0; ni < 8; ni++) {
            int col = n0 + wn * 64 + ni * 8 + tig * 2;
            float bs0 = bias1[col]     + (MODE == 0 ? bias2[col]     : 0.f);
            float bs1 = bias1[col + 1] + (MODE == 0 ? bias2[col + 1] : 0.f);
#pragma unroll
            for (int half = 0; half < 2; half++) {
                int mrow = m0 + wm * 32 + mi * 16 + grp + half * 8;
                if (mrow < MM) {
                    size_t off;
                    if (MODE == 0) {
                        off = (size_t)mrow * N;
                    } else {
                        int t = mrow >> 5, b = mrow & 31;
                        off = ((size_t)(b * TT + t + 1)) * N;
                    }
                    Out[off + col]     = c[mi][ni][half * 2 + 0] + bs0;
                    Out[off + col + 1] = c[mi][ni][half * 2 + 1] + bs1;
                }
            }
        }
    }
}

// -------------------- LSTM step (R1-PROVEN, fp32, per-step launch) ----------
// Only change vs R14: hidden-state store goes to g_hs_h as fp16 (same
// __float2half rounding the GEMM applied anyway).
#define LSTM_SMEM ((32 * 516 + 16 * 32) * 4)

__global__ void lstm_step(const float* __restrict__ Whh, int t) {
    extern __shared__ float sm[];
    float* shh = sm;             // [32][516] padded h (prev step)
    float* sg  = sm + 32 * 516;  // [16][32] gate values

    int tid = threadIdx.x;
    const float* hin = g_h[t & 1];
#pragma unroll
    for (int i = 0; i < 16; i++) {
        int s = tid + i * 256;           // 4096 float4 slots
        int row = s >> 7, c4 = s & 127;
        float4 v = *(const float4*)&hin[row * 512 + c4 * 4];
        *(float4*)&shh[row * 516 + c4 * 4] = v;
    }
    __syncthreads();

    int wid = tid >> 5, lane = tid & 31;
#pragma unroll
    for (int rr = 0; rr < 2; rr++) {
        int r = wid * 2 + rr;
        int gidx = r >> 2, du = r & 3;
        int u = blockIdx.x * 4 + du;
        int j = gidx * 512 + u;
        const float4* wp = (const float4*)(Whh + (size_t)j * 512);
        const float4* hp = (const float4*)&shh[lane * 516];
        float acc = 0.f;
#pragma unroll 4
        for (int kkk = 0; kkk < 128; kkk++) {
            float4 w4 = __ldg(&wp[kkk]);    // uniform across warp (broadcast)
            float4 h4 = hp[kkk];
            acc += w4.x * h4.x + w4.y * h4.y + w4.z * h4.z + w4.w * h4.w;
        }
        acc += g_pre[((size_t)t * 32 + lane) * (size_t)G4 + j];
        sg[r * 32 + lane] = acc;
    }
    __syncthreads();

    if (tid < 128) {
        int du = tid >> 5, b = tid & 31;
        int u  = blockIdx.x * 4 + du;
        float gi = sg[(0 + du) * 32 + b];
        float gf = sg[(4 + du) * 32 + b];
        float gg = sg[(8 + du) * 32 + b];
        float go = sg[(12 + du) * 32 + b];
        float si = 1.f / (1.f + __expf(-gi));
        float sf = 1.f / (1.f + __expf(-gf));
        float so = 1.f / (1.f + __expf(-go));
        float tg = tanhf(gg);
        float cn = sf * g_c[b * 512 + u] + si * tg;
        float hn = so * tanhf(cn);
        g_c[b * 512 + u] = cn;
        g_h[(t + 1) & 1][b * 512 + u] = hn;
        g_hs_h[((size_t)t * 32 + b) * 512 + u] = __float2half_rn(hn);
    }
}

// -------------------- launch --------------------
extern "C" void kernel_launch(void* const* d_in, const int* in_sizes, int n_in,
                              void* d_out, int out_size) {
    const float* features = (const float*)d_in[0];
    const void*  captions = d_in[1];
    const float* embed    = (const float*)d_in[2];
    const float* W_ih     = (const float*)d_in[3];
    const float* W_hh     = (const float*)d_in[4];
    const float* b_ih     = (const float*)d_in[5];
    const float* b_hh     = (const float*)d_in[6];
    const float* fc_w     = (const float*)d_in[7];
    const float* fc_b     = (const float*)d_in[8];
    float* out = (float*)d_out;

    cudaFuncSetAttribute(lstm_step, cudaFuncAttributeMaxDynamicSharedMemorySize,
                         LSTM_SMEM);

    detect_cap64<<<1, 32>>>((const int*)captions);
    build_xseq<<<dim3(63, 32), 128>>>(features, captions, embed);
    init_state<<<64, 256>>>();
    zero_out0<<<dim3(125, 32), 256>>>(out);

    // one-time fp16 conversions of the two GEMM B matrices
    to_half4<<<(G4 * KK / 4 + 255) / 256, 256>>>(W_ih, g_wih_h, G4 * KK / 4);
    to_half4<<<(int)(((size_t)VV * KK / 4 + 255) / 256), 256>>>(fc_w, g_fcw_h,
                                                                (int)((size_t)VV * KK / 4));

    // pre-gates for all timesteps: [2016,512] @ [512,2048] + b_ih + b_hh
    gemm_f16<0, G4><<<dim3(G4 / 128, 16), 256>>>(g_wih_h, b_ih, b_hh, nullptr);

    // sequential recurrence (R1-proven per-step kernel)
    for (int t = 0; t < NSTEP; t++)
        lstm_step<<<128, 256, LSTM_SMEM>>>(W_hh, t);

    // output projection: [2016,512] @ [512,32000], scattered to out[b][t+1][:]
    gemm_f16<1, VV><<<dim3(VV / 128, 16), 256>>>(g_fcw_h, fc_b, nullptr, out);
}